// round 15
// baseline (speedup 1.0000x reference)
#include <cuda_runtime.h>
#include <cstdint>
#include <math_constants.h>

#define NN 100000
#define EE 1600000
#define TILE 128
#define NTILE (EE / TILE)          // 12500 exactly
#define NSCANB 98
#define B16STRIDE 36               // u32 words per B row (fp16): !=0 mod 32
#define DSTRIDE 133
#define USTRIDE 72
#define NODE_TILES 782             // ceil(100000/128)

// ---------------- static device scratch ----------------------------------
__device__ int      g_cnt[NN];
__device__ int      g_off[NN];
__device__ int      g_rank[EE];
__device__ int      g_bsum[NSCANB];
__device__ int      g_srcs[EE];
__device__ int      g_enode[EE];
// g_U/g_V columns stored in hcol-PERMUTED order (fp16 fragment half pairing)
__device__ __align__(256) float    g_U[NN * 64];
__device__ __align__(256) float    g_V[NN * 64];
__device__ __align__(256) unsigned g_agg1[NN * 64];
__device__ __align__(256) unsigned g_agg2[NN * 64];

// ---------------- helpers -------------------------------------------------
__device__ __forceinline__ uint32_t tf32(float f) {
    uint32_t r;
    asm("cvt.rna.tf32.f32 %0, %1;" : "=r"(r) : "f"(f));
    return r;
}
// pack {lo, hi} floats into one f16x2 word (first asm src -> HIGH half)
__device__ __forceinline__ uint32_t pack_h2(float lo, float hi) {
    uint32_t d;
    asm("cvt.rn.f16x2.f32 %0, %1, %2;" : "=r"(d) : "f"(hi), "f"(lo));
    return d;
}
__device__ __forceinline__ unsigned ord_enc(float f) {
    unsigned u = __float_as_uint(f);
    return (u & 0x80000000u) ? ~u : (u | 0x80000000u);
}
__device__ __forceinline__ float ord_dec(unsigned u) {
    return (u & 0x80000000u) ? __uint_as_float(u ^ 0x80000000u) : __uint_as_float(~u);
}
__device__ __forceinline__ void redmax(unsigned* p, unsigned v) {
    asm volatile("red.global.max.u32 [%0], %1;" :: "l"(p), "r"(v) : "memory");
}
// tf32-fragment column permutation (k, k+4 adjacent) - k_uvmma internal only
__device__ __forceinline__ int gcol(int k) {
    return ((k >> 3) << 3) + ((k & 3) << 1) + ((k >> 2) & 1);
}
// fp16-fragment half permutation: within each 16-group, half order is
// (k=0,1),(k=8,9),(k=2,3),(k=10,11),(k=4,5),(k=12,13),(k=6,7),(k=14,15)
__device__ __forceinline__ int hcol(int k) {
    return ((k >> 4) << 4) + (((k & 7) >> 1) << 2) + (((k >> 3) & 1) << 1) + (k & 1);
}
__device__ __forceinline__ uint32_t sptr(const void* p) {
    return (uint32_t)__cvta_generic_to_shared(p);
}
__device__ __forceinline__ void lds_v2(uint32_t& a, uint32_t& b, uint32_t addr) {
    asm volatile("ld.shared.v2.b32 {%0,%1}, [%2];"
                 : "=r"(a), "=r"(b) : "r"(addr) : "memory");
}

// ---------------- k_init: zero scratch + layer-1 U,V (K=7, hcol) ----------
__global__ void __launch_bounds__(1024) k_init(const float* __restrict__ x,
                                               const float* __restrict__ W1a,
                                               const float* __restrict__ b1a) {
    unsigned i = blockIdx.x * 1024u + threadIdx.x;
    if (i < NN * 64) { g_agg1[i] = 0u; g_agg2[i] = 0u; }
    if (i < NN) g_cnt[i] = 0;

    if (blockIdx.x < 3125) {
        __shared__ float sW[14 * 64];
        __shared__ float sb[64];
        for (int t = threadIdx.x; t < 14 * 64; t += 1024) sW[t] = W1a[t];
        for (int t = threadIdx.x; t < 64; t += 1024) sb[t] = b1a[t];
        __syncthreads();
        int wid = threadIdx.x >> 5, lane = threadIdx.x & 31;
        int n = blockIdx.x * 32 + wid;          // 3125*32 = 100000 exactly
        int c0 = 2 * lane, c1 = c0 + 1;
        float xv[7];
#pragma unroll
        for (int k = 0; k < 7; k++) xv[k] = x[n * 7 + k];
        float u0 = sb[c0], u1 = sb[c1], v0 = 0.f, v1 = 0.f;
#pragma unroll
        for (int k = 0; k < 7; k++) {
            float wt0 = sW[k * 64 + c0], wt1 = sW[k * 64 + c1];
            float wb0 = sW[(7 + k) * 64 + c0], wb1 = sW[(7 + k) * 64 + c1];
            u0 = fmaf(xv[k], wt0 - wb0, u0);
            u1 = fmaf(xv[k], wt1 - wb1, u1);
            v0 = fmaf(xv[k], wb0, v0);
            v1 = fmaf(xv[k], wb1, v1);
        }
        int p0 = hcol(c0), p1 = hcol(c1);
        g_U[n * 64 + p0] = u0; g_U[n * 64 + p1] = u1;
        g_V[n * 64 + p0] = v0; g_V[n * 64 + p1] = v1;
    }
}

// ---------------- count + rank --------------------------------------------
__global__ void k_count(const int* __restrict__ ei) {
    int e = blockIdx.x * blockDim.x + threadIdx.x;
    if (e < EE) {
        int d = ei[EE + e];
        g_rank[e] = atomicAdd(&g_cnt[d], 1);
    }
}

// ---------------- 3-kernel exclusive scan ---------------------------------
__global__ void __launch_bounds__(1024) k_scan1() {
    __shared__ int ws[32];
    int i = blockIdx.x * 1024 + threadIdx.x;
    int v = (i < NN) ? g_cnt[i] : 0;
    int x = v;
#pragma unroll
    for (int o = 1; o < 32; o <<= 1) {
        int y = __shfl_up_sync(0xffffffffu, x, o);
        if ((threadIdx.x & 31) >= o) x += y;
    }
    if ((threadIdx.x & 31) == 31) ws[threadIdx.x >> 5] = x;
    __syncthreads();
    if (threadIdx.x < 32) {
        int y = ws[threadIdx.x];
#pragma unroll
        for (int o = 1; o < 32; o <<= 1) {
            int z = __shfl_up_sync(0xffffffffu, y, o);
            if (threadIdx.x >= o) y += z;
        }
        ws[threadIdx.x] = y;
    }
    __syncthreads();
    int wsum = (threadIdx.x >= 32) ? ws[(threadIdx.x >> 5) - 1] : 0;
    int incl = x + wsum;
    if (i < NN) g_off[i] = incl - v;
    if (threadIdx.x == 1023) g_bsum[blockIdx.x] = incl;
}
__global__ void __launch_bounds__(128) k_scan2() {
    __shared__ int ws[4];
    int t = threadIdx.x, lane = t & 31, wp = t >> 5;
    int v = (t < NSCANB) ? g_bsum[t] : 0;
    int x = v;
#pragma unroll
    for (int o = 1; o < 32; o <<= 1) {
        int y = __shfl_up_sync(0xffffffffu, x, o);
        if (lane >= o) x += y;
    }
    if (lane == 31) ws[wp] = x;
    __syncthreads();
    int base = 0;
#pragma unroll
    for (int w = 0; w < 4; w++) if (w < wp) base += ws[w];
    if (t < NSCANB) g_bsum[t] = base + x - v;   // exclusive
}
__global__ void __launch_bounds__(1024) k_scan3() {
    int i = blockIdx.x * 1024 + threadIdx.x;
    if (i < NN) g_off[i] += g_bsum[blockIdx.x];
}

// ---------------- fill sorted edge arrays (no atomics) --------------------
__global__ void k_fill(const int* __restrict__ ei) {
    int e = blockIdx.x * blockDim.x + threadIdx.x;
    if (e >= EE) return;
    int s = ei[e], d = ei[EE + e];
    int idx = g_off[d] + g_rank[e];
    g_srcs[idx] = s;
    g_enode[idx] = d;
}

// ---------------- hot kernel: fp16 m16n8k16 over sorted edge tiles --------
#define MMA_SMEM_WORDS (TILE * B16STRIDE + 64 * DSTRIDE + TILE)
#define MMA_SMEM_BYTES (MMA_SMEM_WORDS * 4)

template <int LAYER>
__global__ void __launch_bounds__(256, 2) k_mma(const float* __restrict__ Wb) {
    unsigned* __restrict__ agg = (LAYER == 0) ? g_agg1 : g_agg2;
    extern __shared__ uint32_t smem[];
    uint32_t* Bs = smem;                                    // [128][B16STRIDE] half2 words
    float*    Ds = (float*)(smem + TILE * B16STRIDE);       // [64][DSTRIDE]
    int*   snode = (int*)(smem + TILE * B16STRIDE + 64 * DSTRIDE);

    const int tid = threadIdx.x, wid = tid >> 5, lane = tid & 31;
    const int g = lane >> 2, r = lane & 3;
    const int m0 = 16 * (wid & 3);
    const int n0b = 64 * (wid >> 2);

    // preload A fragments (Wb^T, fp16): 4 k16-steps x 4 regs
    // a0:(m=g,k=2r,2r+1) a1:(g+8,same) a2:(g,k+8) a3:(g+8,k+8)
    uint32_t aw[4][4];
#pragma unroll
    for (int s = 0; s < 4; s++) {
        int k0 = 16 * s + 2 * r;
        aw[s][0] = pack_h2(Wb[k0 * 64 + m0 + g],       Wb[(k0 + 1) * 64 + m0 + g]);
        aw[s][1] = pack_h2(Wb[k0 * 64 + m0 + g + 8],   Wb[(k0 + 1) * 64 + m0 + g + 8]);
        aw[s][2] = pack_h2(Wb[(k0 + 8) * 64 + m0 + g], Wb[(k0 + 9) * 64 + m0 + g]);
        aw[s][3] = pack_h2(Wb[(k0 + 8) * 64 + m0 + g + 8], Wb[(k0 + 9) * 64 + m0 + g + 8]);
    }

    const int half = lane >> 4, l16 = lane & 15;   // build-phase lane split

    for (int tt = blockIdx.x; tt < NTILE; tt += gridDim.x) {
        int e0w = tt * TILE + wid * 16;
        // ---- build B tile: fp32 gather+sum+relu, ONE fp16 rounding
        {
            int myv = (lane < 16) ? g_srcs[e0w + lane] : g_enode[e0w + (lane - 16)];
            if (lane >= 16) snode[wid * 16 + lane - 16] = myv;
#pragma unroll
            for (int j = 0; j < 8; j++) {
                int ei2 = 2 * j + half;                       // edge in [0,16)
                int s = __shfl_sync(0xffffffffu, myv, ei2);
                int d = __shfl_sync(0xffffffffu, myv, 16 + ei2);
                float4 u = *(const float4*)&g_U[d * 64 + 4 * l16];
                float4 v = *(const float4*)&g_V[s * 64 + 4 * l16];
                uint32_t w0 = pack_h2(fmaxf(u.x + v.x, 0.f), fmaxf(u.y + v.y, 0.f));
                uint32_t w1 = pack_h2(fmaxf(u.z + v.z, 0.f), fmaxf(u.w + v.w, 0.f));
                uint32_t addr = sptr(&Bs[(wid * 16 + ei2) * B16STRIDE + 2 * l16]);
                asm volatile("st.shared.v2.b32 [%0], {%1,%2};"
                             :: "r"(addr), "r"(w0), "r"(w1) : "memory");
            }
        }
        __syncthreads();

        // ---- MMA: warp covers ch [m0,m0+16) x edges [n0b, n0b+64)
#pragma unroll
        for (int j = 0; j < 8; j++) {
            int n0 = n0b + 8 * j;
            float c0 = 0.f, c1 = 0.f, c2 = 0.f, c3 = 0.f;
            uint32_t bp = sptr(&Bs[(n0 + g) * B16STRIDE + 2 * r]);
#pragma unroll
            for (int s = 0; s < 4; s++) {
                uint32_t b0, b1;
                lds_v2(b0, b1, bp + 32 * s);                 // 8 words per k16 step
                asm volatile(
                    "mma.sync.aligned.m16n8k16.row.col.f32.f16.f16.f32 "
                    "{%0,%1,%2,%3}, {%4,%5,%6,%7}, {%8,%9}, {%0,%1,%2,%3};"
                    : "+f"(c0), "+f"(c1), "+f"(c2), "+f"(c3)
                    : "r"(aw[s][0]), "r"(aw[s][1]), "r"(aw[s][2]), "r"(aw[s][3]),
                      "r"(b0), "r"(b1));
            }
            int e = n0 + 2 * r;
            Ds[(m0 + g) * DSTRIDE + e]         = c0;
            Ds[(m0 + g) * DSTRIDE + e + 1]     = c1;
            Ds[(m0 + g + 8) * DSTRIDE + e]     = c2;
            Ds[(m0 + g + 8) * DSTRIDE + e + 1] = c3;
        }
        __syncthreads();

        // ---- epilogue: segmented max; thread = (channel, edge-quarter)
        {
            int ch = tid & 63, qq = tid >> 6;
            int es = qq * 32;
            float acc = -CUDART_INF_F;
            int cur = snode[es];
            const float* dp = &Ds[ch * DSTRIDE];
#pragma unroll 8
            for (int e = es; e < es + 32; e++) {
                int nid = snode[e];
                float v = dp[e];
                if (nid != cur) {
                    redmax(&agg[cur * 64 + ch], ord_enc(acc));
                    cur = nid;
                    acc = -CUDART_INF_F;
                }
                acc = fmaxf(acc, v);
            }
            redmax(&agg[cur * 64 + ch], ord_enc(acc));
        }
        __syncthreads();
    }
}

// ---------------- fused layer-2 U,V: h = relu(agg1+b1b); [U|V] = h@Wc -----
#define UV_SMEM_WORDS (2 * 128 * USTRIDE + 128)
#define UV_SMEM_BYTES (UV_SMEM_WORDS * 4)

__global__ void __launch_bounds__(256, 2) k_uvmma(const float* __restrict__ W2a,
                                                  const float* __restrict__ b2a,
                                                  const float* __restrict__ b1b) {
    extern __shared__ uint32_t sm2[];
    uint32_t* Hs = sm2;                          // [128 nodes][USTRIDE]
    uint32_t* Ws = sm2 + 128 * USTRIDE;          // [128 outs][USTRIDE]
    float* sb2 = (float*)(sm2 + 2 * 128 * USTRIDE);
    float* sb1 = sb2 + 64;

    int tid = threadIdx.x, wid = tid >> 5, lane = tid & 31;
    int g = lane >> 2, r = lane & 3;
    if (tid < 64) { sb2[tid] = b2a[tid]; sb1[tid] = b1b[tid]; }
    // stage combined weights:  out n<64: Wt-Wb (U),  n>=64: Wb (V)
    for (int i = tid; i < 128 * 64; i += 256) {
        int n = i >> 6, k = i & 63;
        float w = (n < 64) ? (W2a[k * 64 + n] - W2a[(64 + k) * 64 + n])
                           : W2a[(64 + k) * 64 + (n - 64)];
        Ws[n * USTRIDE + gcol(k)] = tf32(w);
    }
    __syncthreads();

    int m0 = wid * 16;
    for (int tt = blockIdx.x; tt < NODE_TILES; tt += gridDim.x) {
        int base = tt * 128;
        // build h tile (bias + relu + NaN->0 for empty nodes)
        for (int i = tid; i < 128 * 32; i += 256) {
            int row = i >> 5, kp = i & 31;
            int gg = kp >> 2, q = kp & 3, k = gg * 8 + q;
            int node = base + row;
            float h0 = 0.f, h1 = 0.f;
            if (node < NN) {
                h0 = fmaxf(ord_dec(g_agg1[node * 64 + k]) + sb1[k], 0.f);
                h1 = fmaxf(ord_dec(g_agg1[node * 64 + k + 4]) + sb1[k + 4], 0.f);
            }
            uint32_t q0 = tf32(h0), q1 = tf32(h1);
            asm volatile("st.shared.v2.b32 [%0], {%1,%2};"
                         :: "r"(sptr(&Hs[row * USTRIDE + gg * 8 + 2 * q])), "r"(q0), "r"(q1) : "memory");
        }
        __syncthreads();
        // A fragments for this warp's 16 nodes
        uint32_t a[8][4];
#pragma unroll
        for (int kk = 0; kk < 8; kk++) {
            lds_v2(a[kk][0], a[kk][2], sptr(&Hs[(m0 + g) * USTRIDE + 2 * r + 8 * kk]));
            lds_v2(a[kk][1], a[kk][3], sptr(&Hs[(m0 + g + 8) * USTRIDE + 2 * r + 8 * kk]));
        }
#pragma unroll
        for (int j = 0; j < 16; j++) {
            float c0 = 0.f, c1 = 0.f, c2 = 0.f, c3 = 0.f;
            uint32_t wp = sptr(&Ws[(8 * j + g) * USTRIDE + 2 * r]);
#pragma unroll
            for (int kk = 0; kk < 8; kk++) {
                uint32_t b0, b1;
                lds_v2(b0, b1, wp + 32 * kk);
                asm volatile(
                    "mma.sync.aligned.m16n8k8.row.col.f32.tf32.tf32.f32 "
                    "{%0,%1,%2,%3}, {%4,%5,%6,%7}, {%8,%9}, {%0,%1,%2,%3};"
                    : "+f"(c0), "+f"(c1), "+f"(c2), "+f"(c3)
                    : "r"(a[kk][0]), "r"(a[kk][1]), "r"(a[kk][2]), "r"(a[kk][3]),
                      "r"(b0), "r"(b1));
            }
            int col = 8 * j + 2 * r;
            int n1 = base + m0 + g, n2 = n1 + 8;
            if (col < 64) {
                int p0 = hcol(col), p1 = hcol(col + 1);
                float bx = sb2[col], by = sb2[col + 1];
                if (n1 < NN) { g_U[n1 * 64 + p0] = c0 + bx; g_U[n1 * 64 + p1] = c1 + by; }
                if (n2 < NN) { g_U[n2 * 64 + p0] = c2 + bx; g_U[n2 * 64 + p1] = c3 + by; }
            } else {
                int p0 = hcol(col - 64), p1 = hcol(col - 63);
                if (n1 < NN) { g_V[n1 * 64 + p0] = c0; g_V[n1 * 64 + p1] = c1; }
                if (n2 < NN) { g_V[n2 * 64 + p0] = c2; g_V[n2 * 64 + p1] = c3; }
            }
        }
        __syncthreads();
    }
}

// ---------------- final head ----------------------------------------------
__global__ void __launch_bounds__(128) k_final(const float* __restrict__ b2b,
                                               const float* __restrict__ Wl,
                                               const float* __restrict__ bl,
                                               float* __restrict__ out) {
    int warp = threadIdx.x >> 5, lane = threadIdx.x & 31;
    int i = blockIdx.x * 4 + warp;
    if (i >= NN) return;
    int c0 = 2 * lane, c1 = c0 + 1;
    float a0 = fmaxf(ord_dec(g_agg2[i * 64 + c0]) + b2b[c0], 0.f);
    float a1 = fmaxf(ord_dec(g_agg2[i * 64 + c1]) + b2b[c1], 0.f);
    float p = a0 * Wl[c0] + a1 * Wl[c1];
#pragma unroll
    for (int off = 16; off; off >>= 1) p += __shfl_xor_sync(0xffffffffu, p, off);
    if (lane == 0) out[i] = p + bl[0];
}

extern "C" void kernel_launch(void* const* d_in, const int* in_sizes, int n_in,
                              void* d_out, int out_size) {
    const float* x   = (const float*)d_in[0];
    const int*   ei  = (const int*)d_in[1];
    const float* W1a = (const float*)d_in[2];
    const float* b1a = (const float*)d_in[3];
    const float* W1b = (const float*)d_in[4];
    const float* b1b = (const float*)d_in[5];
    const float* W2a = (const float*)d_in[6];
    const float* b2a = (const float*)d_in[7];
    const float* W2b = (const float*)d_in[8];
    const float* b2b = (const float*)d_in[9];
    const float* Wl  = (const float*)d_in[10];
    const float* bl  = (const float*)d_in[11];
    float* out = (float*)d_out;

    cudaFuncSetAttribute(k_mma<0>, cudaFuncAttributeMaxDynamicSharedMemorySize, MMA_SMEM_BYTES);
    cudaFuncSetAttribute(k_mma<1>, cudaFuncAttributeMaxDynamicSharedMemorySize, MMA_SMEM_BYTES);
    cudaFuncSetAttribute(k_uvmma, cudaFuncAttributeMaxDynamicSharedMemorySize, UV_SMEM_BYTES);

    k_init<<<6250, 1024>>>(x, W1a, b1a);
    k_count<<<(EE + 255) / 256, 256>>>(ei);
    k_scan1<<<NSCANB, 1024>>>();
    k_scan2<<<1, 128>>>();
    k_scan3<<<NSCANB, 1024>>>();
    k_fill<<<(EE + 255) / 256, 256>>>(ei);
    k_mma<0><<<444, 256, MMA_SMEM_BYTES>>>(W1b);
    k_uvmma<<<296, 256, UV_SMEM_BYTES>>>(W2a, b2a, b1b);
    k_mma<1><<<444, 256, MMA_SMEM_BYTES>>>(W2b);
    k_final<<<(NN + 3) / 4, 128>>>(b2b, Wl, bl, out);
}

// round 16
// speedup vs baseline: 1.3244x; 1.3244x over previous
#include <cuda_runtime.h>
#include <cstdint>
#include <math_constants.h>

#define NN 100000
#define EE 1600000
#define TILE 128
#define NTILE (EE / TILE)          // 12500 exactly
#define NSCANB 98
#define B16STRIDE 40               // == 8 mod 32 -> conflict-free v2 within LDS.64 phase
#define DSTRIDE 133
#define USTRIDE 72
#define NODE_TILES 782             // ceil(100000/128)

// ---------------- static device scratch ----------------------------------
__device__ int      g_cnt[NN];
__device__ int      g_off[NN];
__device__ int      g_rank[EE];
__device__ int      g_bsum[NSCANB];
__device__ int      g_srcs[EE];
__device__ int      g_enode[EE];
// g_U/g_V columns stored in hcol-PERMUTED order (fp16 fragment half pairing)
__device__ __align__(256) float    g_U[NN * 64];
__device__ __align__(256) float    g_V[NN * 64];
__device__ __align__(256) unsigned g_agg1[NN * 64];
__device__ __align__(256) unsigned g_agg2[NN * 64];

// ---------------- helpers -------------------------------------------------
__device__ __forceinline__ uint32_t tf32(float f) {
    uint32_t r;
    asm("cvt.rna.tf32.f32 %0, %1;" : "=r"(r) : "f"(f));
    return r;
}
// pack {lo, hi} floats into one f16x2 word (first asm src -> HIGH half)
__device__ __forceinline__ uint32_t pack_h2(float lo, float hi) {
    uint32_t d;
    asm("cvt.rn.f16x2.f32 %0, %1, %2;" : "=r"(d) : "f"(hi), "f"(lo));
    return d;
}
__device__ __forceinline__ unsigned ord_enc(float f) {
    unsigned u = __float_as_uint(f);
    return (u & 0x80000000u) ? ~u : (u | 0x80000000u);
}
__device__ __forceinline__ float ord_dec(unsigned u) {
    return (u & 0x80000000u) ? __uint_as_float(u ^ 0x80000000u) : __uint_as_float(~u);
}
__device__ __forceinline__ void redmax(unsigned* p, unsigned v) {
    asm volatile("red.global.max.u32 [%0], %1;" :: "l"(p), "r"(v) : "memory");
}
// tf32-fragment column permutation (k, k+4 adjacent) - k_uvmma internal only
__device__ __forceinline__ int gcol(int k) {
    return ((k >> 3) << 3) + ((k & 3) << 1) + ((k >> 2) & 1);
}
// fp16-fragment half permutation: within each 16-group, half order is
// (k=0,1),(k=8,9),(k=2,3),(k=10,11),(k=4,5),(k=12,13),(k=6,7),(k=14,15)
__device__ __forceinline__ int hcol(int k) {
    return ((k >> 4) << 4) + (((k & 7) >> 1) << 2) + (((k >> 3) & 1) << 1) + (k & 1);
}
__device__ __forceinline__ uint32_t sptr(const void* p) {
    return (uint32_t)__cvta_generic_to_shared(p);
}
__device__ __forceinline__ void lds_v2(uint32_t& a, uint32_t& b, uint32_t addr) {
    asm volatile("ld.shared.v2.b32 {%0,%1}, [%2];"
                 : "=r"(a), "=r"(b) : "r"(addr) : "memory");
}

// ---------------- k_init: zero scratch + layer-1 U,V (K=7, hcol) ----------
__global__ void __launch_bounds__(1024) k_init(const float* __restrict__ x,
                                               const float* __restrict__ W1a,
                                               const float* __restrict__ b1a) {
    unsigned i = blockIdx.x * 1024u + threadIdx.x;
    if (i < NN * 64) { g_agg1[i] = 0u; g_agg2[i] = 0u; }
    if (i < NN) g_cnt[i] = 0;

    if (blockIdx.x < 3125) {
        __shared__ float sW[14 * 64];
        __shared__ float sb[64];
        for (int t = threadIdx.x; t < 14 * 64; t += 1024) sW[t] = W1a[t];
        for (int t = threadIdx.x; t < 64; t += 1024) sb[t] = b1a[t];
        __syncthreads();
        int wid = threadIdx.x >> 5, lane = threadIdx.x & 31;
        int n = blockIdx.x * 32 + wid;          // 3125*32 = 100000 exactly
        int c0 = 2 * lane, c1 = c0 + 1;
        float xv[7];
#pragma unroll
        for (int k = 0; k < 7; k++) xv[k] = x[n * 7 + k];
        float u0 = sb[c0], u1 = sb[c1], v0 = 0.f, v1 = 0.f;
#pragma unroll
        for (int k = 0; k < 7; k++) {
            float wt0 = sW[k * 64 + c0], wt1 = sW[k * 64 + c1];
            float wb0 = sW[(7 + k) * 64 + c0], wb1 = sW[(7 + k) * 64 + c1];
            u0 = fmaf(xv[k], wt0 - wb0, u0);
            u1 = fmaf(xv[k], wt1 - wb1, u1);
            v0 = fmaf(xv[k], wb0, v0);
            v1 = fmaf(xv[k], wb1, v1);
        }
        int p0 = hcol(c0), p1 = hcol(c1);
        g_U[n * 64 + p0] = u0; g_U[n * 64 + p1] = u1;
        g_V[n * 64 + p0] = v0; g_V[n * 64 + p1] = v1;
    }
}

// ---------------- count + rank --------------------------------------------
__global__ void k_count(const int* __restrict__ ei) {
    int e = blockIdx.x * blockDim.x + threadIdx.x;
    if (e < EE) {
        int d = ei[EE + e];
        g_rank[e] = atomicAdd(&g_cnt[d], 1);
    }
}

// ---------------- 3-kernel exclusive scan ---------------------------------
__global__ void __launch_bounds__(1024) k_scan1() {
    __shared__ int ws[32];
    int i = blockIdx.x * 1024 + threadIdx.x;
    int v = (i < NN) ? g_cnt[i] : 0;
    int x = v;
#pragma unroll
    for (int o = 1; o < 32; o <<= 1) {
        int y = __shfl_up_sync(0xffffffffu, x, o);
        if ((threadIdx.x & 31) >= o) x += y;
    }
    if ((threadIdx.x & 31) == 31) ws[threadIdx.x >> 5] = x;
    __syncthreads();
    if (threadIdx.x < 32) {
        int y = ws[threadIdx.x];
#pragma unroll
        for (int o = 1; o < 32; o <<= 1) {
            int z = __shfl_up_sync(0xffffffffu, y, o);
            if (threadIdx.x >= o) y += z;
        }
        ws[threadIdx.x] = y;
    }
    __syncthreads();
    int wsum = (threadIdx.x >= 32) ? ws[(threadIdx.x >> 5) - 1] : 0;
    int incl = x + wsum;
    if (i < NN) g_off[i] = incl - v;
    if (threadIdx.x == 1023) g_bsum[blockIdx.x] = incl;
}
__global__ void __launch_bounds__(128) k_scan2() {
    __shared__ int ws[4];
    int t = threadIdx.x, lane = t & 31, wp = t >> 5;
    int v = (t < NSCANB) ? g_bsum[t] : 0;
    int x = v;
#pragma unroll
    for (int o = 1; o < 32; o <<= 1) {
        int y = __shfl_up_sync(0xffffffffu, x, o);
        if (lane >= o) x += y;
    }
    if (lane == 31) ws[wp] = x;
    __syncthreads();
    int base = 0;
#pragma unroll
    for (int w = 0; w < 4; w++) if (w < wp) base += ws[w];
    if (t < NSCANB) g_bsum[t] = base + x - v;   // exclusive
}
__global__ void __launch_bounds__(1024) k_scan3() {
    int i = blockIdx.x * 1024 + threadIdx.x;
    if (i < NN) g_off[i] += g_bsum[blockIdx.x];
}

// ---------------- fill sorted edge arrays (no atomics) --------------------
__global__ void k_fill(const int* __restrict__ ei) {
    int e = blockIdx.x * blockDim.x + threadIdx.x;
    if (e >= EE) return;
    int s = ei[e], d = ei[EE + e];
    int idx = g_off[d] + g_rank[e];
    g_srcs[idx] = s;
    g_enode[idx] = d;
}

// ---------------- hot kernel: fp16 m16n8k16 over sorted edge tiles --------
#define MMA_SMEM_WORDS (TILE * B16STRIDE + 64 * DSTRIDE + TILE)
#define MMA_SMEM_BYTES (MMA_SMEM_WORDS * 4)

template <int LAYER>
__global__ void __launch_bounds__(256, 2) k_mma(const float* __restrict__ Wb) {
    unsigned* __restrict__ agg = (LAYER == 0) ? g_agg1 : g_agg2;
    extern __shared__ uint32_t smem[];
    uint32_t* Bs = smem;                                    // [128][B16STRIDE] half2 words
    float*    Ds = (float*)(smem + TILE * B16STRIDE);       // [64][DSTRIDE]
    int*   snode = (int*)(smem + TILE * B16STRIDE + 64 * DSTRIDE);

    const int tid = threadIdx.x, wid = tid >> 5, lane = tid & 31;
    const int g = lane >> 2, r = lane & 3;
    const int m0 = 16 * (wid & 3);
    const int n0b = 64 * (wid >> 2);

    // preload A fragments (Wb^T, fp16): 4 k16-steps x 4 regs
    uint32_t aw[4][4];
#pragma unroll
    for (int s = 0; s < 4; s++) {
        int k0 = 16 * s + 2 * r;
        aw[s][0] = pack_h2(Wb[k0 * 64 + m0 + g],       Wb[(k0 + 1) * 64 + m0 + g]);
        aw[s][1] = pack_h2(Wb[k0 * 64 + m0 + g + 8],   Wb[(k0 + 1) * 64 + m0 + g + 8]);
        aw[s][2] = pack_h2(Wb[(k0 + 8) * 64 + m0 + g], Wb[(k0 + 9) * 64 + m0 + g]);
        aw[s][3] = pack_h2(Wb[(k0 + 8) * 64 + m0 + g + 8], Wb[(k0 + 9) * 64 + m0 + g + 8]);
    }

    const int half = lane >> 4, l16 = lane & 15;   // build-phase lane split

    for (int tt = blockIdx.x; tt < NTILE; tt += gridDim.x) {
        int e0w = tt * TILE + wid * 16;
        // ---- build B tile: fp32 gather+sum+relu, ONE fp16 rounding
        {
            int myv = (lane < 16) ? g_srcs[e0w + lane] : g_enode[e0w + (lane - 16)];
            if (lane >= 16) snode[wid * 16 + lane - 16] = myv;
#pragma unroll
            for (int j = 0; j < 8; j++) {
                int ei2 = 2 * j + half;                       // edge in [0,16)
                int s = __shfl_sync(0xffffffffu, myv, ei2);
                int d = __shfl_sync(0xffffffffu, myv, 16 + ei2);
                float4 u = *(const float4*)&g_U[d * 64 + 4 * l16];
                float4 v = *(const float4*)&g_V[s * 64 + 4 * l16];
                uint32_t w0 = pack_h2(fmaxf(u.x + v.x, 0.f), fmaxf(u.y + v.y, 0.f));
                uint32_t w1 = pack_h2(fmaxf(u.z + v.z, 0.f), fmaxf(u.w + v.w, 0.f));
                uint32_t addr = sptr(&Bs[(wid * 16 + ei2) * B16STRIDE + 2 * l16]);
                asm volatile("st.shared.v2.b32 [%0], {%1,%2};"
                             :: "r"(addr), "r"(w0), "r"(w1) : "memory");
            }
        }
        __syncthreads();

        // ---- MMA: warp covers ch [m0,m0+16) x edges [n0b, n0b+64)
#pragma unroll
        for (int j = 0; j < 8; j++) {
            int n0 = n0b + 8 * j;
            float c0 = 0.f, c1 = 0.f, c2 = 0.f, c3 = 0.f;
            uint32_t bp = sptr(&Bs[(n0 + g) * B16STRIDE + 2 * r]);
#pragma unroll
            for (int s = 0; s < 4; s++) {
                uint32_t b0, b1;
                lds_v2(b0, b1, bp + 32 * s);                 // 8 words per k16 step
                asm volatile(
                    "mma.sync.aligned.m16n8k16.row.col.f32.f16.f16.f32 "
                    "{%0,%1,%2,%3}, {%4,%5,%6,%7}, {%8,%9}, {%0,%1,%2,%3};"
                    : "+f"(c0), "+f"(c1), "+f"(c2), "+f"(c3)
                    : "r"(aw[s][0]), "r"(aw[s][1]), "r"(aw[s][2]), "r"(aw[s][3]),
                      "r"(b0), "r"(b1));
            }
            int e = n0 + 2 * r;
            Ds[(m0 + g) * DSTRIDE + e]         = c0;
            Ds[(m0 + g) * DSTRIDE + e + 1]     = c1;
            Ds[(m0 + g + 8) * DSTRIDE + e]     = c2;
            Ds[(m0 + g + 8) * DSTRIDE + e + 1] = c3;
        }
        __syncthreads();

        // ---- epilogue: segmented max; thread = (channel, edge-quarter)
        {
            int ch = tid & 63, qq = tid >> 6;
            int es = qq * 32;
            float acc = -CUDART_INF_F;
            int cur = snode[es];
            const float* dp = &Ds[ch * DSTRIDE];
#pragma unroll 8
            for (int e = es; e < es + 32; e++) {
                int nid = snode[e];
                float v = dp[e];
                if (nid != cur) {
                    redmax(&agg[cur * 64 + ch], ord_enc(acc));
                    cur = nid;
                    acc = -CUDART_INF_F;
                }
                acc = fmaxf(acc, v);
            }
            redmax(&agg[cur * 64 + ch], ord_enc(acc));
        }
        __syncthreads();
    }
}

// ---------------- fused layer-2 U,V: h = relu(agg1+b1b); [U|V] = h@Wc -----
#define UV_SMEM_WORDS (2 * 128 * USTRIDE + 128)
#define UV_SMEM_BYTES (UV_SMEM_WORDS * 4)

__global__ void __launch_bounds__(256, 2) k_uvmma(const float* __restrict__ W2a,
                                                  const float* __restrict__ b2a,
                                                  const float* __restrict__ b1b) {
    extern __shared__ uint32_t sm2[];
    uint32_t* Hs = sm2;                          // [128 nodes][USTRIDE]
    uint32_t* Ws = sm2 + 128 * USTRIDE;          // [128 outs][USTRIDE]
    float* sb2 = (float*)(sm2 + 2 * 128 * USTRIDE);
    float* sb1 = sb2 + 64;

    int tid = threadIdx.x, wid = tid >> 5, lane = tid & 31;
    int g = lane >> 2, r = lane & 3;
    if (tid < 64) { sb2[tid] = b2a[tid]; sb1[tid] = b1b[tid]; }
    // stage combined weights:  out n<64: Wt-Wb (U),  n>=64: Wb (V)
    for (int i = tid; i < 128 * 64; i += 256) {
        int n = i >> 6, k = i & 63;
        float w = (n < 64) ? (W2a[k * 64 + n] - W2a[(64 + k) * 64 + n])
                           : W2a[(64 + k) * 64 + (n - 64)];
        Ws[n * USTRIDE + gcol(k)] = tf32(w);
    }
    __syncthreads();

    int m0 = wid * 16;
    for (int tt = blockIdx.x; tt < NODE_TILES; tt += gridDim.x) {
        int base = tt * 128;
        // build h tile (bias + relu + NaN->0 for empty nodes)
        for (int i = tid; i < 128 * 32; i += 256) {
            int row = i >> 5, kp = i & 31;
            int gg = kp >> 2, q = kp & 3, k = gg * 8 + q;
            int node = base + row;
            float h0 = 0.f, h1 = 0.f;
            if (node < NN) {
                h0 = fmaxf(ord_dec(g_agg1[node * 64 + k]) + sb1[k], 0.f);
                h1 = fmaxf(ord_dec(g_agg1[node * 64 + k + 4]) + sb1[k + 4], 0.f);
            }
            uint32_t q0 = tf32(h0), q1 = tf32(h1);
            asm volatile("st.shared.v2.b32 [%0], {%1,%2};"
                         :: "r"(sptr(&Hs[row * USTRIDE + gg * 8 + 2 * q])), "r"(q0), "r"(q1) : "memory");
        }
        __syncthreads();
        // A fragments for this warp's 16 nodes
        uint32_t a[8][4];
#pragma unroll
        for (int kk = 0; kk < 8; kk++) {
            lds_v2(a[kk][0], a[kk][2], sptr(&Hs[(m0 + g) * USTRIDE + 2 * r + 8 * kk]));
            lds_v2(a[kk][1], a[kk][3], sptr(&Hs[(m0 + g + 8) * USTRIDE + 2 * r + 8 * kk]));
        }
#pragma unroll
        for (int j = 0; j < 16; j++) {
            float c0 = 0.f, c1 = 0.f, c2 = 0.f, c3 = 0.f;
            uint32_t wp = sptr(&Ws[(8 * j + g) * USTRIDE + 2 * r]);
#pragma unroll
            for (int kk = 0; kk < 8; kk++) {
                uint32_t b0, b1;
                lds_v2(b0, b1, wp + 32 * kk);
                asm volatile(
                    "mma.sync.aligned.m16n8k8.row.col.f32.tf32.tf32.f32 "
                    "{%0,%1,%2,%3}, {%4,%5,%6,%7}, {%8,%9}, {%0,%1,%2,%3};"
                    : "+f"(c0), "+f"(c1), "+f"(c2), "+f"(c3)
                    : "r"(a[kk][0]), "r"(a[kk][1]), "r"(a[kk][2]), "r"(a[kk][3]),
                      "r"(b0), "r"(b1));
            }
            int col = 8 * j + 2 * r;
            int n1 = base + m0 + g, n2 = n1 + 8;
            if (col < 64) {
                int p0 = hcol(col), p1 = hcol(col + 1);
                float bx = sb2[col], by = sb2[col + 1];
                if (n1 < NN) { g_U[n1 * 64 + p0] = c0 + bx; g_U[n1 * 64 + p1] = c1 + by; }
                if (n2 < NN) { g_U[n2 * 64 + p0] = c2 + bx; g_U[n2 * 64 + p1] = c3 + by; }
            } else {
                int p0 = hcol(col - 64), p1 = hcol(col - 63);
                if (n1 < NN) { g_V[n1 * 64 + p0] = c0; g_V[n1 * 64 + p1] = c1; }
                if (n2 < NN) { g_V[n2 * 64 + p0] = c2; g_V[n2 * 64 + p1] = c3; }
            }
        }
        __syncthreads();
    }
}

// ---------------- final head ----------------------------------------------
__global__ void __launch_bounds__(128) k_final(const float* __restrict__ b2b,
                                               const float* __restrict__ Wl,
                                               const float* __restrict__ bl,
                                               float* __restrict__ out) {
    int warp = threadIdx.x >> 5, lane = threadIdx.x & 31;
    int i = blockIdx.x * 4 + warp;
    if (i >= NN) return;
    int c0 = 2 * lane, c1 = c0 + 1;
    float a0 = fmaxf(ord_dec(g_agg2[i * 64 + c0]) + b2b[c0], 0.f);
    float a1 = fmaxf(ord_dec(g_agg2[i * 64 + c1]) + b2b[c1], 0.f);
    float p = a0 * Wl[c0] + a1 * Wl[c1];
#pragma unroll
    for (int off = 16; off; off >>= 1) p += __shfl_xor_sync(0xffffffffu, p, off);
    if (lane == 0) out[i] = p + bl[0];
}

extern "C" void kernel_launch(void* const* d_in, const int* in_sizes, int n_in,
                              void* d_out, int out_size) {
    const float* x   = (const float*)d_in[0];
    const int*   ei  = (const int*)d_in[1];
    const float* W1a = (const float*)d_in[2];
    const float* b1a = (const float*)d_in[3];
    const float* W1b = (const float*)d_in[4];
    const float* b1b = (const float*)d_in[5];
    const float* W2a = (const float*)d_in[6];
    const float* b2a = (const float*)d_in[7];
    const float* W2b = (const float*)d_in[8];
    const float* b2b = (const float*)d_in[9];
    const float* Wl  = (const float*)d_in[10];
    const float* bl  = (const float*)d_in[11];
    float* out = (float*)d_out;

    cudaFuncSetAttribute(k_mma<0>, cudaFuncAttributeMaxDynamicSharedMemorySize, MMA_SMEM_BYTES);
    cudaFuncSetAttribute(k_mma<1>, cudaFuncAttributeMaxDynamicSharedMemorySize, MMA_SMEM_BYTES);
    cudaFuncSetAttribute(k_uvmma, cudaFuncAttributeMaxDynamicSharedMemorySize, UV_SMEM_BYTES);

    k_init<<<6250, 1024>>>(x, W1a, b1a);
    k_count<<<(EE + 255) / 256, 256>>>(ei);
    k_scan1<<<NSCANB, 1024>>>();
    k_scan2<<<1, 128>>>();
    k_scan3<<<NSCANB, 1024>>>();
    k_fill<<<(EE + 255) / 256, 256>>>(ei);
    k_mma<0><<<296, 256, MMA_SMEM_BYTES>>>(W1b);
    k_uvmma<<<296, 256, UV_SMEM_BYTES>>>(W2a, b2a, b1b);
    k_mma<1><<<296, 256, MMA_SMEM_BYTES>>>(W2b);
    k_final<<<(NN + 3) / 4, 128>>>(b2b, Wl, bl, out);
}

// round 17
// speedup vs baseline: 1.4492x; 1.0942x over previous
#include <cuda_runtime.h>
#include <cstdint>
#include <math_constants.h>

#define NN 100000
#define EE 1600000
#define TILE 128
#define NTILE (EE / TILE)          // 12500 exactly
#define NSCANB 98
#define B16STRIDE 40               // == 8 mod 32 -> conflict-free v2 within LDS.64 phase
#define DSTRIDE 133
#define USTRIDE 72
#define NODE_TILES 782             // ceil(100000/128)
#define GRID3 444                  // 148 SMs x 3 blocks -> exactly one wave

// ---------------- static device scratch ----------------------------------
__device__ int      g_cnt[NN];
__device__ int      g_off[NN];
__device__ int      g_rank[EE];
__device__ int      g_bsum[NSCANB];
__device__ int      g_srcs[EE];
__device__ int      g_enode[EE];
// g_U/g_V columns stored in hcol-PERMUTED order (fp16 fragment half pairing)
__device__ __align__(256) float    g_U[NN * 64];
__device__ __align__(256) float    g_V[NN * 64];
__device__ __align__(256) unsigned g_agg1[NN * 64];
__device__ __align__(256) unsigned g_agg2[NN * 64];

// ---------------- helpers -------------------------------------------------
__device__ __forceinline__ uint32_t tf32(float f) {
    uint32_t r;
    asm("cvt.rna.tf32.f32 %0, %1;" : "=r"(r) : "f"(f));
    return r;
}
// pack {lo, hi} floats into one f16x2 word (first asm src -> HIGH half)
__device__ __forceinline__ uint32_t pack_h2(float lo, float hi) {
    uint32_t d;
    asm("cvt.rn.f16x2.f32 %0, %1, %2;" : "=r"(d) : "f"(hi), "f"(lo));
    return d;
}
__device__ __forceinline__ unsigned ord_enc(float f) {
    unsigned u = __float_as_uint(f);
    return (u & 0x80000000u) ? ~u : (u | 0x80000000u);
}
__device__ __forceinline__ float ord_dec(unsigned u) {
    return (u & 0x80000000u) ? __uint_as_float(u ^ 0x80000000u) : __uint_as_float(~u);
}
__device__ __forceinline__ void redmax(unsigned* p, unsigned v) {
    asm volatile("red.global.max.u32 [%0], %1;" :: "l"(p), "r"(v) : "memory");
}
// tf32-fragment column permutation (k, k+4 adjacent) - k_uvmma internal only
__device__ __forceinline__ int gcol(int k) {
    return ((k >> 3) << 3) + ((k & 3) << 1) + ((k >> 2) & 1);
}
// fp16-fragment half permutation
__device__ __forceinline__ int hcol(int k) {
    return ((k >> 4) << 4) + (((k & 7) >> 1) << 2) + (((k >> 3) & 1) << 1) + (k & 1);
}
__device__ __forceinline__ uint32_t sptr(const void* p) {
    return (uint32_t)__cvta_generic_to_shared(p);
}
__device__ __forceinline__ void lds_v2(uint32_t& a, uint32_t& b, uint32_t addr) {
    asm volatile("ld.shared.v2.b32 {%0,%1}, [%2];"
                 : "=r"(a), "=r"(b) : "r"(addr) : "memory");
}

// ---------------- k_init: zero scratch + layer-1 U,V (K=7, hcol) ----------
__global__ void __launch_bounds__(1024) k_init(const float* __restrict__ x,
                                               const float* __restrict__ W1a,
                                               const float* __restrict__ b1a) {
    unsigned i = blockIdx.x * 1024u + threadIdx.x;
    if (i < NN * 64) { g_agg1[i] = 0u; g_agg2[i] = 0u; }
    if (i < NN) g_cnt[i] = 0;

    if (blockIdx.x < 3125) {
        __shared__ float sW[14 * 64];
        __shared__ float sb[64];
        for (int t = threadIdx.x; t < 14 * 64; t += 1024) sW[t] = W1a[t];
        for (int t = threadIdx.x; t < 64; t += 1024) sb[t] = b1a[t];
        __syncthreads();
        int wid = threadIdx.x >> 5, lane = threadIdx.x & 31;
        int n = blockIdx.x * 32 + wid;          // 3125*32 = 100000 exactly
        int c0 = 2 * lane, c1 = c0 + 1;
        float xv[7];
#pragma unroll
        for (int k = 0; k < 7; k++) xv[k] = x[n * 7 + k];
        float u0 = sb[c0], u1 = sb[c1], v0 = 0.f, v1 = 0.f;
#pragma unroll
        for (int k = 0; k < 7; k++) {
            float wt0 = sW[k * 64 + c0], wt1 = sW[k * 64 + c1];
            float wb0 = sW[(7 + k) * 64 + c0], wb1 = sW[(7 + k) * 64 + c1];
            u0 = fmaf(xv[k], wt0 - wb0, u0);
            u1 = fmaf(xv[k], wt1 - wb1, u1);
            v0 = fmaf(xv[k], wb0, v0);
            v1 = fmaf(xv[k], wb1, v1);
        }
        int p0 = hcol(c0), p1 = hcol(c1);
        g_U[n * 64 + p0] = u0; g_U[n * 64 + p1] = u1;
        g_V[n * 64 + p0] = v0; g_V[n * 64 + p1] = v1;
    }
}

// ---------------- count + rank --------------------------------------------
__global__ void k_count(const int* __restrict__ ei) {
    int e = blockIdx.x * blockDim.x + threadIdx.x;
    if (e < EE) {
        int d = ei[EE + e];
        g_rank[e] = atomicAdd(&g_cnt[d], 1);
    }
}

// ---------------- 3-kernel exclusive scan ---------------------------------
__global__ void __launch_bounds__(1024) k_scan1() {
    __shared__ int ws[32];
    int i = blockIdx.x * 1024 + threadIdx.x;
    int v = (i < NN) ? g_cnt[i] : 0;
    int x = v;
#pragma unroll
    for (int o = 1; o < 32; o <<= 1) {
        int y = __shfl_up_sync(0xffffffffu, x, o);
        if ((threadIdx.x & 31) >= o) x += y;
    }
    if ((threadIdx.x & 31) == 31) ws[threadIdx.x >> 5] = x;
    __syncthreads();
    if (threadIdx.x < 32) {
        int y = ws[threadIdx.x];
#pragma unroll
        for (int o = 1; o < 32; o <<= 1) {
            int z = __shfl_up_sync(0xffffffffu, y, o);
            if (threadIdx.x >= o) y += z;
        }
        ws[threadIdx.x] = y;
    }
    __syncthreads();
    int wsum = (threadIdx.x >= 32) ? ws[(threadIdx.x >> 5) - 1] : 0;
    int incl = x + wsum;
    if (i < NN) g_off[i] = incl - v;
    if (threadIdx.x == 1023) g_bsum[blockIdx.x] = incl;
}
__global__ void __launch_bounds__(128) k_scan2() {
    __shared__ int ws[4];
    int t = threadIdx.x, lane = t & 31, wp = t >> 5;
    int v = (t < NSCANB) ? g_bsum[t] : 0;
    int x = v;
#pragma unroll
    for (int o = 1; o < 32; o <<= 1) {
        int y = __shfl_up_sync(0xffffffffu, x, o);
        if (lane >= o) x += y;
    }
    if (lane == 31) ws[wp] = x;
    __syncthreads();
    int base = 0;
#pragma unroll
    for (int w = 0; w < 4; w++) if (w < wp) base += ws[w];
    if (t < NSCANB) g_bsum[t] = base + x - v;   // exclusive
}
__global__ void __launch_bounds__(1024) k_scan3() {
    int i = blockIdx.x * 1024 + threadIdx.x;
    if (i < NN) g_off[i] += g_bsum[blockIdx.x];
}

// ---------------- fill sorted edge arrays (no atomics) --------------------
__global__ void k_fill(const int* __restrict__ ei) {
    int e = blockIdx.x * blockDim.x + threadIdx.x;
    if (e >= EE) return;
    int s = ei[e], d = ei[EE + e];
    int idx = g_off[d] + g_rank[e];
    g_srcs[idx] = s;
    g_enode[idx] = d;
}

// ---------------- hot kernel: fp16 m16n8k16 over sorted edge tiles --------
// occupancy 3; per-tile phases: [MMA] sync [epilogue(t) + build(t+1)] sync
#define MMA_SMEM_WORDS (TILE * B16STRIDE + 64 * DSTRIDE + 2 * TILE)
#define MMA_SMEM_BYTES (MMA_SMEM_WORDS * 4)

template <int LAYER>
__global__ void __launch_bounds__(256, 3) k_mma(const float* __restrict__ Wb) {
    unsigned* __restrict__ agg = (LAYER == 0) ? g_agg1 : g_agg2;
    extern __shared__ uint32_t smem[];
    uint32_t* Bs = smem;                                    // [128][B16STRIDE] half2 words
    float*    Ds = (float*)(smem + TILE * B16STRIDE);       // [64][DSTRIDE]
    int*   snode = (int*)(smem + TILE * B16STRIDE + 64 * DSTRIDE); // [2][128]

    const int tid = threadIdx.x, wid = tid >> 5, lane = tid & 31;
    const int g = lane >> 2, r = lane & 3;
    const int m0 = 16 * (wid & 3);
    const int n0b = 64 * (wid >> 2);

    // preload A fragments (Wb^T, fp16): 4 k16-steps x 4 regs
    uint32_t aw[4][4];
#pragma unroll
    for (int s = 0; s < 4; s++) {
        int k0 = 16 * s + 2 * r;
        aw[s][0] = pack_h2(Wb[k0 * 64 + m0 + g],       Wb[(k0 + 1) * 64 + m0 + g]);
        aw[s][1] = pack_h2(Wb[k0 * 64 + m0 + g + 8],   Wb[(k0 + 1) * 64 + m0 + g + 8]);
        aw[s][2] = pack_h2(Wb[(k0 + 8) * 64 + m0 + g], Wb[(k0 + 9) * 64 + m0 + g]);
        aw[s][3] = pack_h2(Wb[(k0 + 8) * 64 + m0 + g + 8], Wb[(k0 + 9) * 64 + m0 + g + 8]);
    }

    const int half = lane >> 4, l16 = lane & 15;   // build-phase lane split

    // build B tile tt into Bs and snode[qq]
    auto build = [&](int tt, int qq) {
        int e0w = tt * TILE + wid * 16;
        int* sn = snode + qq * TILE;
        int myv = (lane < 16) ? g_srcs[e0w + lane] : g_enode[e0w + (lane - 16)];
        if (lane >= 16) sn[wid * 16 + lane - 16] = myv;
#pragma unroll
        for (int j = 0; j < 8; j++) {
            int ei2 = 2 * j + half;                       // edge in [0,16)
            int s = __shfl_sync(0xffffffffu, myv, ei2);
            int d = __shfl_sync(0xffffffffu, myv, 16 + ei2);
            float4 u = *(const float4*)&g_U[d * 64 + 4 * l16];
            float4 v = *(const float4*)&g_V[s * 64 + 4 * l16];
            uint32_t w0 = pack_h2(fmaxf(u.x + v.x, 0.f), fmaxf(u.y + v.y, 0.f));
            uint32_t w1 = pack_h2(fmaxf(u.z + v.z, 0.f), fmaxf(u.w + v.w, 0.f));
            uint32_t addr = sptr(&Bs[(wid * 16 + ei2) * B16STRIDE + 2 * l16]);
            asm volatile("st.shared.v2.b32 [%0], {%1,%2};"
                         :: "r"(addr), "r"(w0), "r"(w1) : "memory");
        }
    };

    // number of tiles for this block (grid-stride)
    int nt = 0;
    for (int t = blockIdx.x; t < NTILE; t += GRID3) nt++;
    if (nt == 0) return;

    build(blockIdx.x, 0);
    __syncthreads();

    int q = 0;
    for (int idx = 0; idx < nt; idx++) {
        // ---- MMA: warp covers ch [m0,m0+16) x edges [n0b, n0b+64)
#pragma unroll
        for (int j = 0; j < 8; j++) {
            int n0 = n0b + 8 * j;
            float c0 = 0.f, c1 = 0.f, c2 = 0.f, c3 = 0.f;
            uint32_t bp = sptr(&Bs[(n0 + g) * B16STRIDE + 2 * r]);
#pragma unroll
            for (int s = 0; s < 4; s++) {
                uint32_t b0, b1;
                lds_v2(b0, b1, bp + 32 * s);                 // 8 words per k16 step
                asm volatile(
                    "mma.sync.aligned.m16n8k16.row.col.f32.f16.f16.f32 "
                    "{%0,%1,%2,%3}, {%4,%5,%6,%7}, {%8,%9}, {%0,%1,%2,%3};"
                    : "+f"(c0), "+f"(c1), "+f"(c2), "+f"(c3)
                    : "r"(aw[s][0]), "r"(aw[s][1]), "r"(aw[s][2]), "r"(aw[s][3]),
                      "r"(b0), "r"(b1));
            }
            int e = n0 + 2 * r;
            Ds[(m0 + g) * DSTRIDE + e]         = c0;
            Ds[(m0 + g) * DSTRIDE + e + 1]     = c1;
            Ds[(m0 + g + 8) * DSTRIDE + e]     = c2;
            Ds[(m0 + g + 8) * DSTRIDE + e + 1] = c3;
        }
        __syncthreads();

        // ---- merged phase: build(t+1) into Bs/snode[q^1]  +  epilogue(t)
        if (idx + 1 < nt) build(blockIdx.x + (idx + 1) * GRID3, q ^ 1);
        {
            int ch = tid & 63, qq = tid >> 6;
            int es = qq * 32;
            const int* sn = snode + q * TILE;
            float acc = -CUDART_INF_F;
            int cur = sn[es];
            const float* dp = &Ds[ch * DSTRIDE];
#pragma unroll 8
            for (int e = es; e < es + 32; e++) {
                int nid = sn[e];
                float v = dp[e];
                if (nid != cur) {
                    redmax(&agg[cur * 64 + ch], ord_enc(acc));
                    cur = nid;
                    acc = -CUDART_INF_F;
                }
                acc = fmaxf(acc, v);
            }
            redmax(&agg[cur * 64 + ch], ord_enc(acc));
        }
        __syncthreads();
        q ^= 1;
    }
}

// ---------------- fused layer-2 U,V: h = relu(agg1+b1b); [U|V] = h@Wc -----
#define UV_SMEM_WORDS (2 * 128 * USTRIDE + 128)
#define UV_SMEM_BYTES (UV_SMEM_WORDS * 4)

__global__ void __launch_bounds__(256, 2) k_uvmma(const float* __restrict__ W2a,
                                                  const float* __restrict__ b2a,
                                                  const float* __restrict__ b1b) {
    extern __shared__ uint32_t sm2[];
    uint32_t* Hs = sm2;                          // [128 nodes][USTRIDE]
    uint32_t* Ws = sm2 + 128 * USTRIDE;          // [128 outs][USTRIDE]
    float* sb2 = (float*)(sm2 + 2 * 128 * USTRIDE);
    float* sb1 = sb2 + 64;

    int tid = threadIdx.x, wid = tid >> 5, lane = tid & 31;
    int g = lane >> 2, r = lane & 3;
    if (tid < 64) { sb2[tid] = b2a[tid]; sb1[tid] = b1b[tid]; }
    // stage combined weights:  out n<64: Wt-Wb (U),  n>=64: Wb (V)
    for (int i = tid; i < 128 * 64; i += 256) {
        int n = i >> 6, k = i & 63;
        float w = (n < 64) ? (W2a[k * 64 + n] - W2a[(64 + k) * 64 + n])
                           : W2a[(64 + k) * 64 + (n - 64)];
        Ws[n * USTRIDE + gcol(k)] = tf32(w);
    }
    __syncthreads();

    int m0 = wid * 16;
    for (int tt = blockIdx.x; tt < NODE_TILES; tt += gridDim.x) {
        int base = tt * 128;
        // build h tile (bias + relu + NaN->0 for empty nodes)
        for (int i = tid; i < 128 * 32; i += 256) {
            int row = i >> 5, kp = i & 31;
            int gg = kp >> 2, q = kp & 3, k = gg * 8 + q;
            int node = base + row;
            float h0 = 0.f, h1 = 0.f;
            if (node < NN) {
                h0 = fmaxf(ord_dec(g_agg1[node * 64 + k]) + sb1[k], 0.f);
                h1 = fmaxf(ord_dec(g_agg1[node * 64 + k + 4]) + sb1[k + 4], 0.f);
            }
            uint32_t q0 = tf32(h0), q1 = tf32(h1);
            asm volatile("st.shared.v2.b32 [%0], {%1,%2};"
                         :: "r"(sptr(&Hs[row * USTRIDE + gg * 8 + 2 * q])), "r"(q0), "r"(q1) : "memory");
        }
        __syncthreads();
        // A fragments for this warp's 16 nodes
        uint32_t a[8][4];
#pragma unroll
        for (int kk = 0; kk < 8; kk++) {
            lds_v2(a[kk][0], a[kk][2], sptr(&Hs[(m0 + g) * USTRIDE + 2 * r + 8 * kk]));
            lds_v2(a[kk][1], a[kk][3], sptr(&Hs[(m0 + g + 8) * USTRIDE + 2 * r + 8 * kk]));
        }
#pragma unroll
        for (int j = 0; j < 16; j++) {
            float c0 = 0.f, c1 = 0.f, c2 = 0.f, c3 = 0.f;
            uint32_t wp = sptr(&Ws[(8 * j + g) * USTRIDE + 2 * r]);
#pragma unroll
            for (int kk = 0; kk < 8; kk++) {
                uint32_t b0, b1;
                lds_v2(b0, b1, wp + 32 * kk);
                asm volatile(
                    "mma.sync.aligned.m16n8k8.row.col.f32.tf32.tf32.f32 "
                    "{%0,%1,%2,%3}, {%4,%5,%6,%7}, {%8,%9}, {%0,%1,%2,%3};"
                    : "+f"(c0), "+f"(c1), "+f"(c2), "+f"(c3)
                    : "r"(a[kk][0]), "r"(a[kk][1]), "r"(a[kk][2]), "r"(a[kk][3]),
                      "r"(b0), "r"(b1));
            }
            int col = 8 * j + 2 * r;
            int n1 = base + m0 + g, n2 = n1 + 8;
            if (col < 64) {
                int p0 = hcol(col), p1 = hcol(col + 1);
                float bx = sb2[col], by = sb2[col + 1];
                if (n1 < NN) { g_U[n1 * 64 + p0] = c0 + bx; g_U[n1 * 64 + p1] = c1 + by; }
                if (n2 < NN) { g_U[n2 * 64 + p0] = c2 + bx; g_U[n2 * 64 + p1] = c3 + by; }
            } else {
                int p0 = hcol(col - 64), p1 = hcol(col - 63);
                if (n1 < NN) { g_V[n1 * 64 + p0] = c0; g_V[n1 * 64 + p1] = c1; }
                if (n2 < NN) { g_V[n2 * 64 + p0] = c2; g_V[n2 * 64 + p1] = c3; }
            }
        }
        __syncthreads();
    }
}

// ---------------- final head ----------------------------------------------
__global__ void __launch_bounds__(128) k_final(const float* __restrict__ b2b,
                                               const float* __restrict__ Wl,
                                               const float* __restrict__ bl,
                                               float* __restrict__ out) {
    int warp = threadIdx.x >> 5, lane = threadIdx.x & 31;
    int i = blockIdx.x * 4 + warp;
    if (i >= NN) return;
    int c0 = 2 * lane, c1 = c0 + 1;
    float a0 = fmaxf(ord_dec(g_agg2[i * 64 + c0]) + b2b[c0], 0.f);
    float a1 = fmaxf(ord_dec(g_agg2[i * 64 + c1]) + b2b[c1], 0.f);
    float p = a0 * Wl[c0] + a1 * Wl[c1];
#pragma unroll
    for (int off = 16; off; off >>= 1) p += __shfl_xor_sync(0xffffffffu, p, off);
    if (lane == 0) out[i] = p + bl[0];
}

extern "C" void kernel_launch(void* const* d_in, const int* in_sizes, int n_in,
                              void* d_out, int out_size) {
    const float* x   = (const float*)d_in[0];
    const int*   ei  = (const int*)d_in[1];
    const float* W1a = (const float*)d_in[2];
    const float* b1a = (const float*)d_in[3];
    const float* W1b = (const float*)d_in[4];
    const float* b1b = (const float*)d_in[5];
    const float* W2a = (const float*)d_in[6];
    const float* b2a = (const float*)d_in[7];
    const float* W2b = (const float*)d_in[8];
    const float* b2b = (const float*)d_in[9];
    const float* Wl  = (const float*)d_in[10];
    const float* bl  = (const float*)d_in[11];
    float* out = (float*)d_out;

    cudaFuncSetAttribute(k_mma<0>, cudaFuncAttributeMaxDynamicSharedMemorySize, MMA_SMEM_BYTES);
    cudaFuncSetAttribute(k_mma<1>, cudaFuncAttributeMaxDynamicSharedMemorySize, MMA_SMEM_BYTES);
    cudaFuncSetAttribute(k_uvmma, cudaFuncAttributeMaxDynamicSharedMemorySize, UV_SMEM_BYTES);

    k_init<<<6250, 1024>>>(x, W1a, b1a);
    k_count<<<(EE + 255) / 256, 256>>>(ei);
    k_scan1<<<NSCANB, 1024>>>();
    k_scan2<<<1, 128>>>();
    k_scan3<<<NSCANB, 1024>>>();
    k_fill<<<(EE + 255) / 256, 256>>>(ei);
    k_mma<0><<<GRID3, 256, MMA_SMEM_BYTES>>>(W1b);
    k_uvmma<<<296, 256, UV_SMEM_BYTES>>>(W2a, b2a, b1b);
    k_mma<1><<<GRID3, 256, MMA_SMEM_BYTES>>>(W2b);
    k_final<<<(NN + 3) / 4, 128>>>(b2b, Wl, bl, out);
}